// round 14
// baseline (speedup 1.0000x reference)
#include <cuda_runtime.h>
#include <cuda_fp16.h>
#include <cstdint>

// Problem constants
#define T_  64
#define B_  128
#define N_  1024
#define TB  8192          // T_*B_
#define BN_ (B_*N_)       // 131072
#define VTH 1.0f
#define EPS 1e-5f

// -------- scratch (no allocation allowed -> __device__ globals) --------
__device__ float d_h1[TB * N_];            // 32 MB  linear1 output [tb, m]
__device__ float d_h2[TB * N_];            // 32 MB  linear2 output [tb, m]
__device__ float d_psum[2 * 64 * N_];      // BN partials [mat][mtile][col]
__device__ float d_psq [2 * 64 * N_];      // BN sum-of-squares partials
__device__ float d_scale[2 * N_];          // gamma * rsqrt(var+eps)
__device__ float d_bias [2 * N_];          // beta - mean*scale
__device__ int   d_ssum_i[T_ * B_];        // spatial spike counts (int, exact)
__device__ float d_tsum[B_ * N_];          // temporal_sum [b,m]

// ===================== mma.sync fp16 helper ============================
__device__ __forceinline__ void mma_f16(float* d, const uint32_t* a, const uint32_t* b) {
    asm volatile(
        "mma.sync.aligned.m16n8k16.row.col.f32.f16.f16.f32 "
        "{%0,%1,%2,%3}, {%4,%5,%6,%7}, {%8,%9}, {%0,%1,%2,%3};"
        : "+f"(d[0]), "+f"(d[1]), "+f"(d[2]), "+f"(d[3])
        : "r"(a[0]), "r"(a[1]), "r"(a[2]), "r"(a[3]), "r"(b[0]), "r"(b[1]));
}
// pack two floats' fp16-hi parts and fp16 residuals
__device__ __forceinline__ void split2(float x, float y, uint32_t& hi, uint32_t& lo) {
    __half hx = __float2half_rn(x), hy = __float2half_rn(y);
    float rx = x - __half2float(hx);
    float ry = y - __half2float(hy);
    __half2 h2 = __halves2half2(hx, hy);
    __half2 l2 = __halves2half2(__float2half_rn(rx), __float2half_rn(ry));
    hi = *(uint32_t*)&h2;
    lo = *(uint32_t*)&l2;
}

// ================= 3xFP16 GEMM: H = X @ W^T ===========================
// 128x64 CTA tile, 256 threads (8 warps, 4x2 grid of 32x32 warp tiles),
// K-chunk 32, double-buffered, ONE sync per chunk, __launch_bounds(256,2)
// -> 2 resident CTAs/SM so one CTA's MMA phase covers the other's
// store/barrier/prefetch bubbles. Same MMA count & order as the 128x128
// version (bit-identical results).
#define LDA2 20
#define ATSZ (128 * LDA2)            // A-tile half2 words (2560)
#define BTSZ (64 * LDA2)             // B-tile half2 words (1280)
#define STG2 (2 * ATSZ + 2 * BTSZ)   // per-stage words (7680)
#define AH_ 0
#define AL_ ATSZ
#define BH_ (2 * ATSZ)
#define BL_ (2 * ATSZ + BTSZ)
#define SMEM_BYTES (2 * STG2 * 4)    // 61440 bytes

__global__ __launch_bounds__(256, 2) void gemm_tc(
    const float* __restrict__ X,
    const float* __restrict__ W1,
    const float* __restrict__ W2)
{
    extern __shared__ uint32_t sm[];
    const float* __restrict__ W = blockIdx.z ? W2 : W1;
    float* __restrict__ H = blockIdx.z ? d_h2 : d_h1;
    const int m0 = blockIdx.y * 128;
    const int n0 = blockIdx.x * 64;
    const int tid = threadIdx.x;
    const int lane = tid & 31, w = tid >> 5;
    const int wm = w & 3, wn = w >> 2;        // warp grid 4(m) x 2(n)
    const int qr = lane >> 2, qc = lane & 3;  // quad row/col

    float acc[2][4][4];
    #pragma unroll
    for (int i = 0; i < 2; i++)
        #pragma unroll
        for (int j = 0; j < 4; j++)
            #pragma unroll
            for (int k = 0; k < 4; k++) acc[i][j][k] = 0.f;

    // loaders: A = 128 rows x 8 float4 (4/thread); B = 64 rows x 8 (2/thread)
    const int lra = tid >> 1;           // A row 0..127
    const int sa  = (tid & 1) * 4;      // A float4 slot base
    const int lrb = tid >> 2;           // B row 0..63
    const int sb  = (tid & 3) * 2;      // B float4 slot base

    float4 pa[4], pb[2];
    #pragma unroll
    for (int j = 0; j < 4; j++)
        pa[j] = *(const float4*)&X[(size_t)(m0 + lra) * N_ + (sa + j) * 4];
    #pragma unroll
    for (int j = 0; j < 2; j++)
        pb[j] = *(const float4*)&W[(size_t)(n0 + lrb) * N_ + (sb + j) * 4];

    for (int c = 0; c < 32; c++) {
        uint32_t* S = sm + (c & 1) * STG2;
        #pragma unroll
        for (int j = 0; j < 4; j++) {
            float4 a = pa[j];
            uint32_t h0, l0, h1, l1;
            split2(a.x, a.y, h0, l0);
            split2(a.z, a.w, h1, l1);
            const int o = lra * LDA2 + 2 * (sa + j);
            *(uint2*)&S[AH_ + o] = make_uint2(h0, h1);
            *(uint2*)&S[AL_ + o] = make_uint2(l0, l1);
        }
        #pragma unroll
        for (int j = 0; j < 2; j++) {
            float4 b = pb[j];
            uint32_t h0, l0, h1, l1;
            split2(b.x, b.y, h0, l0);
            split2(b.z, b.w, h1, l1);
            const int o = lrb * LDA2 + 2 * (sb + j);
            *(uint2*)&S[BH_ + o] = make_uint2(h0, h1);
            *(uint2*)&S[BL_ + o] = make_uint2(l0, l1);
        }
        if (c < 31) {
            const int k0 = (c + 1) * 32;
            #pragma unroll
            for (int j = 0; j < 4; j++)
                pa[j] = *(const float4*)&X[(size_t)(m0 + lra) * N_ + k0 + (sa + j) * 4];
            #pragma unroll
            for (int j = 0; j < 2; j++)
                pb[j] = *(const float4*)&W[(size_t)(n0 + lrb) * N_ + k0 + (sb + j) * 4];
        }
        __syncthreads();   // single barrier per chunk
        #pragma unroll
        for (int ks = 0; ks < 2; ks++) {
            const int kp = ks * 8;
            uint32_t aHi[2][4], aLo[2][4], bHi[4][2], bLo[4][2];
            #pragma unroll
            for (int mf = 0; mf < 2; mf++) {
                const int rb = wm * 32 + mf * 16;
                const int r0 = (rb + qr) * LDA2 + kp + qc;
                const int r1 = (rb + 8 + qr) * LDA2 + kp + qc;
                aHi[mf][0] = S[AH_ + r0];
                aHi[mf][1] = S[AH_ + r1];
                aHi[mf][2] = S[AH_ + r0 + 4];
                aHi[mf][3] = S[AH_ + r1 + 4];
                aLo[mf][0] = S[AL_ + r0];
                aLo[mf][1] = S[AL_ + r1];
                aLo[mf][2] = S[AL_ + r0 + 4];
                aLo[mf][3] = S[AL_ + r1 + 4];
            }
            #pragma unroll
            for (int nf = 0; nf < 4; nf++) {
                const int cb = wn * 32 + nf * 8;
                const int r0 = (cb + qr) * LDA2 + kp + qc;
                bHi[nf][0] = S[BH_ + r0];
                bHi[nf][1] = S[BH_ + r0 + 4];
                bLo[nf][0] = S[BL_ + r0];
                bLo[nf][1] = S[BL_ + r0 + 4];
            }
            #pragma unroll
            for (int mf = 0; mf < 2; mf++)
                #pragma unroll
                for (int nf = 0; nf < 4; nf++) {
                    mma_f16(acc[mf][nf], aHi[mf], bHi[nf]);
                    mma_f16(acc[mf][nf], aHi[mf], bLo[nf]);
                    mma_f16(acc[mf][nf], aLo[mf], bHi[nf]);
                }
        }
        // no trailing sync — next chunk writes the other buffer
    }
    __syncthreads();   // protect epilogue smem reuse

    // ---- epilogue: write H tile + fused BN partial sums (deterministic) ----
    #pragma unroll
    for (int mf = 0; mf < 2; mf++) {
        const int r = m0 + wm * 32 + mf * 16 + qr;
        #pragma unroll
        for (int nf = 0; nf < 4; nf++) {
            const int col = n0 + wn * 32 + nf * 8 + qc * 2;
            *(float2*)&H[(size_t)r * N_ + col] =
                make_float2(acc[mf][nf][0], acc[mf][nf][1]);
            *(float2*)&H[(size_t)(r + 8) * N_ + col] =
                make_float2(acc[mf][nf][2], acc[mf][nf][3]);
        }
    }

    float cs[4][2], cq[4][2];
    #pragma unroll
    for (int nf = 0; nf < 4; nf++)
        #pragma unroll
        for (int j = 0; j < 2; j++) {
            float s = 0.f, q = 0.f;
            #pragma unroll
            for (int mf = 0; mf < 2; mf++) {
                float v0 = acc[mf][nf][j], v1 = acc[mf][nf][j + 2];
                s += v0 + v1;
                q += v0 * v0 + v1 * v1;
            }
            #pragma unroll
            for (int off = 16; off >= 4; off >>= 1) {
                s += __shfl_down_sync(0xffffffffu, s, off);
                q += __shfl_down_sync(0xffffffffu, q, off);
            }
            cs[nf][j] = s; cq[nf][j] = q;
        }
    // smem cross-warp combine: [wm][wn][nf][qc][j] (256 + 256 floats)
    float* red = (float*)sm;
    if (qr == 0) {
        #pragma unroll
        for (int nf = 0; nf < 4; nf++)
            #pragma unroll
            for (int j = 0; j < 2; j++) {
                int o = (((wm * 2 + wn) * 4 + nf) * 4 + qc) * 2 + j;
                red[o] = cs[nf][j];
                red[256 + o] = cq[nf][j];
            }
    }
    __syncthreads();
    if (tid < 64) {
        const int col = tid;                 // within tile (64 cols)
        const int wn2 = col >> 5, rem = col & 31;
        const int nf2 = rem >> 3, r2 = rem & 7;
        const int qc2 = r2 >> 1, j2 = r2 & 1;
        float s = 0.f, q = 0.f;
        #pragma unroll
        for (int wm2 = 0; wm2 < 4; wm2++) {
            int o = (((wm2 * 2 + wn2) * 4 + nf2) * 4 + qc2) * 2 + j2;
            s += red[o];
            q += red[256 + o];
        }
        int chunk = blockIdx.z * 64 + blockIdx.y;
        d_psum[(size_t)chunk * N_ + n0 + col] = s;
        d_psq [(size_t)chunk * N_ + n0 + col] = q;
    }
}

// ================= BN finalize (+ zero spatial counters) ===============
__global__ __launch_bounds__(256) void bn_final_kernel(
    const float* __restrict__ g1, const float* __restrict__ b1,
    const float* __restrict__ g2, const float* __restrict__ b2)
{
    const int idx = blockIdx.x * 256 + threadIdx.x;   // mat*N_ + col
    const int mat = idx >> 10;
    const int col = idx & (N_ - 1);
    float s = 0.f, sq = 0.f;
    for (int c = 0; c < 64; c++) {
        s  += d_psum[(size_t)(mat * 64 + c) * N_ + col];
        sq += d_psq [(size_t)(mat * 64 + c) * N_ + col];
    }
    const float inv = 1.f / (float)TB;
    float mean = s * inv;
    float var = sq * inv - mean * mean;
    float gamma = mat ? g2[col] : g1[col];
    float beta  = mat ? b2[col] : b1[col];
    float scale = gamma * rsqrtf(var + EPS);
    d_scale[idx] = scale;
    d_bias[idx] = beta - mean * scale;
    #pragma unroll
    for (int j = 0; j < 4; j++) d_ssum_i[idx * 4 + j] = 0;
}

// ============ Merged LIF branches (spatial + temporal) =================
// blocks [0,512): branch1 (1 feat/thread, ballot counting).
// blocks [512,768): branch2, 2 elems/thread via float2.
__global__ __launch_bounds__(256) void branches_kernel()
{
    const int bx = blockIdx.x;
    const int tid = threadIdx.x;
    if (bx < 512) {
        __shared__ int ssum[T_];
        const int b = bx & 127;
        const int f = (bx >> 7) * 256 + tid;
        const int lane = tid & 31;
        if (tid < T_) ssum[tid] = 0;
        __syncthreads();
        const float sc = d_scale[f];
        const float bi = d_bias[f];
        float v = 0.f;
        for (int t = 0; t < T_; t++) {
            float h = fmaf(d_h1[(size_t)(t * B_ + b) * N_ + f], sc, bi);
            v = fmaf(v, 0.5f, h);
            bool s = (v >= VTH);
            if (s) v = 0.f;
            unsigned bal = __ballot_sync(0xffffffffu, s);
            if (lane == 0) atomicAdd(&ssum[t], __popc(bal));
        }
        __syncthreads();
        if (tid < T_) atomicAdd(&d_ssum_i[tid * B_ + b], ssum[tid]);
    } else {
        const int g = ((bx - 512) * 256 + tid) * 2;     // pair base
        const int m = g & (N_ - 1);
        const float2 sc = *(const float2*)&d_scale[N_ + m];
        const float2 bi = *(const float2*)&d_bias[N_ + m];
        float v0 = 0.f, v1 = 0.f;
        int c0 = 0, c1 = 0;
        #pragma unroll 4
        for (int t = 0; t < T_; t++) {
            float2 h2 = *(const float2*)&d_h2[(size_t)t * BN_ + g];
            float h0 = fmaf(h2.x, sc.x, bi.x);
            float h1 = fmaf(h2.y, sc.y, bi.y);
            v0 = fmaf(v0, 0.5f, h0);
            v1 = fmaf(v1, 0.5f, h1);
            if (v0 >= VTH) { c0++; v0 = 0.f; }
            if (v1 >= VTH) { c1++; v1 = 0.f; }
        }
        *(float2*)&d_tsum[g] = make_float2((float)c0, (float)c1);
    }
}

// ============ Final: gate LIFs + output (2 elems/thread) ===============
__global__ __launch_bounds__(256) void final_kernel(
    const float* __restrict__ X, float* __restrict__ out)
{
    const int g = (blockIdx.x * 256 + threadIdx.x) * 2;  // pair base (b*N_+n)
    const int b = g >> 10;
    __shared__ float ss[T_];
    if (threadIdx.x < T_) ss[threadIdx.x] = (float)d_ssum_i[threadIdx.x * B_ + b];
    __syncthreads();

    const float2 ts = *(const float2*)&d_tsum[g];
    float va0 = 0.f, vb0 = 0.f, va1 = 0.f, vb1 = 0.f;
    #pragma unroll 4
    for (int t = 0; t < T_; t++) {
        float2 xt = *(const float2*)&X[(size_t)t * BN_ + g];
        float st = ss[t];
        va0 = fmaf(va0, 0.5f, xt.x * st);
        va1 = fmaf(va1, 0.5f, xt.y * st);
        float a0 = 0.f, a1 = 0.f;
        if (va0 >= VTH) { a0 = 1.f; va0 = 0.f; }
        if (va1 >= VTH) { a1 = 1.f; va1 = 0.f; }
        vb0 = fmaf(vb0, 0.5f, xt.x * ts.x);
        vb1 = fmaf(vb1, 0.5f, xt.y * ts.y);
        float b0 = 0.f, b1 = 0.f;
        if (vb0 >= VTH) { b0 = 1.f; vb0 = 0.f; }
        if (vb1 >= VTH) { b1 = 1.f; vb1 = 0.f; }
        *(float2*)&out[(size_t)t * BN_ + g] =
            make_float2(xt.x + a0 * b0, xt.y + a1 * b1);
    }
}

// ======================================================================
extern "C" void kernel_launch(void* const* d_in, const int* in_sizes, int n_in,
                              void* d_out, int out_size)
{
    const float* x  = (const float*)d_in[0];
    const float* W1 = (const float*)d_in[1];
    const float* g1 = (const float*)d_in[2];
    const float* b1 = (const float*)d_in[3];
    const float* W2 = (const float*)d_in[4];
    const float* g2 = (const float*)d_in[5];
    const float* b2 = (const float*)d_in[6];
    float* out = (float*)d_out;

    cudaFuncSetAttribute(gemm_tc, cudaFuncAttributeMaxDynamicSharedMemorySize, SMEM_BYTES);

    // 1. Both GEMMs (mma.sync 3xFP16, 128x64 tiles, 2 CTAs/SM)
    dim3 ggrid(N_ / 64, TB / 128, 2);
    gemm_tc<<<ggrid, 256, SMEM_BYTES>>>(x, W1, W2);

    // 2. BN finalize (+ zero spike counters)
    bn_final_kernel<<<(2 * N_) / 256, 256>>>(g1, b1, g2, b2);

    // 3. Merged LIF branches (512 branch1 blocks + 256 branch2 blocks)
    branches_kernel<<<768, 256>>>();

    // 4. Fused gate LIFs + output
    final_kernel<<<BN_ / 512, 256>>>(x, out);
}

// round 15
// speedup vs baseline: 1.2765x; 1.2765x over previous
#include <cuda_runtime.h>
#include <cuda_fp16.h>
#include <cstdint>

// Problem constants
#define T_  64
#define B_  128
#define N_  1024
#define TB  8192          // T_*B_
#define BN_ (B_*N_)       // 131072
#define VTH 1.0f
#define EPS 1e-5f

// -------- scratch (no allocation allowed -> __device__ globals) --------
__device__ float d_h1[TB * N_];            // 32 MB  linear1 output [tb, m]
__device__ float d_h2[TB * N_];            // 32 MB  linear2 output [tb, m]
__device__ float d_psum[2 * 64 * N_];      // BN partials [mat][mtile][col]
__device__ float d_psq [2 * 64 * N_];      // BN sum-of-squares partials
__device__ float d_scale[2 * N_];          // gamma * rsqrt(var+eps)
__device__ float d_bias [2 * N_];          // beta - mean*scale
__device__ int   d_ssum_i[T_ * B_];        // spatial spike counts (int, exact)
__device__ float d_tsum[B_ * N_];          // temporal_sum [b,m]

// ===================== mma.sync fp16 helper ============================
__device__ __forceinline__ void mma_f16(float* d, const uint32_t* a, const uint32_t* b) {
    asm volatile(
        "mma.sync.aligned.m16n8k16.row.col.f32.f16.f16.f32 "
        "{%0,%1,%2,%3}, {%4,%5,%6,%7}, {%8,%9}, {%0,%1,%2,%3};"
        : "+f"(d[0]), "+f"(d[1]), "+f"(d[2]), "+f"(d[3])
        : "r"(a[0]), "r"(a[1]), "r"(a[2]), "r"(a[3]), "r"(b[0]), "r"(b[1]));
}
// pack two floats' fp16-hi parts and fp16 residuals
__device__ __forceinline__ void split2(float x, float y, uint32_t& hi, uint32_t& lo) {
    __half hx = __float2half_rn(x), hy = __float2half_rn(y);
    float rx = x - __half2float(hx);
    float ry = y - __half2float(hy);
    __half2 h2 = __halves2half2(hx, hy);
    __half2 l2 = __halves2half2(__float2half_rn(rx), __float2half_rn(ry));
    hi = *(uint32_t*)&h2;
    lo = *(uint32_t*)&l2;
}

// ================= 3xFP16 GEMM: H = X @ W^T ===========================
// 128x128 CTA tile, 512 threads (16 warps, 32x32 warp tiles), K-chunk 32.
// Double-buffered; ONE sync per chunk (stores of chunk c+1 overlap MMAs of c).
// Best measured configuration (R8/R13): legacy fp16 mma.sync pipe ceiling,
// feed-balanced at 128x128/1-CTA (all perturbations measured slower).
#define LDA2 20
#define TSZ2 (128 * LDA2)            // half2 words per tile (2560)
#define STG2 (4 * TSZ2)              // per-stage words (10240)
#define AH_ 0
#define AL_ TSZ2
#define BH_ (2 * TSZ2)
#define BL_ (3 * TSZ2)
#define SMEM_BYTES (2 * STG2 * 4)    // 81920 bytes

__global__ __launch_bounds__(512, 1) void gemm_tc(
    const float* __restrict__ X,
    const float* __restrict__ W1,
    const float* __restrict__ W2)
{
    extern __shared__ uint32_t sm[];
    const float* __restrict__ W = blockIdx.z ? W2 : W1;
    float* __restrict__ H = blockIdx.z ? d_h2 : d_h1;
    const int m0 = blockIdx.y * 128;
    const int n0 = blockIdx.x * 128;
    const int tid = threadIdx.x;
    const int lane = tid & 31, w = tid >> 5;
    const int wm = w & 3, wn = w >> 2;        // warp grid 4x4
    const int qr = lane >> 2, qc = lane & 3;  // quad row/col

    float acc[2][4][4];
    #pragma unroll
    for (int i = 0; i < 2; i++)
        #pragma unroll
        for (int j = 0; j < 4; j++)
            #pragma unroll
            for (int k = 0; k < 4; k++) acc[i][j][k] = 0.f;

    const int lr = tid >> 3;            // row 0..63 (+64 on pass 1)
    const int lcq = tid & 7;            // which float4 (= 2 half2 pairs)
    const int lc = lcq * 4;

    float4 pa[2], pb[2];
    #pragma unroll
    for (int p = 0; p < 2; p++) {
        int row = lr + p * 64;
        pa[p] = *(const float4*)&X[(size_t)(m0 + row) * N_ + lc];
        pb[p] = *(const float4*)&W[(size_t)(n0 + row) * N_ + lc];
    }

    for (int c = 0; c < 32; c++) {
        uint32_t* S = sm + (c & 1) * STG2;
        #pragma unroll
        for (int p = 0; p < 2; p++) {
            const int row = lr + p * 64;
            float4 a = pa[p], b = pb[p];
            uint32_t ah0, al0, ah1, al1, bh0, bl0, bh1, bl1;
            split2(a.x, a.y, ah0, al0);
            split2(a.z, a.w, ah1, al1);
            split2(b.x, b.y, bh0, bl0);
            split2(b.z, b.w, bh1, bl1);
            const int o = row * LDA2 + 2 * lcq;
            *(uint2*)&S[AH_ + o] = make_uint2(ah0, ah1);
            *(uint2*)&S[AL_ + o] = make_uint2(al0, al1);
            *(uint2*)&S[BH_ + o] = make_uint2(bh0, bh1);
            *(uint2*)&S[BL_ + o] = make_uint2(bl0, bl1);
        }
        if (c < 31) {
            const int k0 = (c + 1) * 32;
            #pragma unroll
            for (int p = 0; p < 2; p++) {
                int row = lr + p * 64;
                pa[p] = *(const float4*)&X[(size_t)(m0 + row) * N_ + k0 + lc];
                pb[p] = *(const float4*)&W[(size_t)(n0 + row) * N_ + k0 + lc];
            }
        }
        __syncthreads();   // single barrier per chunk
        #pragma unroll
        for (int ks = 0; ks < 2; ks++) {
            const int kp = ks * 8;
            uint32_t aHi[2][4], aLo[2][4], bHi[4][2], bLo[4][2];
            #pragma unroll
            for (int mf = 0; mf < 2; mf++) {
                const int rb = wm * 32 + mf * 16;
                const int r0 = (rb + qr) * LDA2 + kp + qc;
                const int r1 = (rb + 8 + qr) * LDA2 + kp + qc;
                aHi[mf][0] = S[AH_ + r0];
                aHi[mf][1] = S[AH_ + r1];
                aHi[mf][2] = S[AH_ + r0 + 4];
                aHi[mf][3] = S[AH_ + r1 + 4];
                aLo[mf][0] = S[AL_ + r0];
                aLo[mf][1] = S[AL_ + r1];
                aLo[mf][2] = S[AL_ + r0 + 4];
                aLo[mf][3] = S[AL_ + r1 + 4];
            }
            #pragma unroll
            for (int nf = 0; nf < 4; nf++) {
                const int cb = wn * 32 + nf * 8;
                const int r0 = (cb + qr) * LDA2 + kp + qc;
                bHi[nf][0] = S[BH_ + r0];
                bHi[nf][1] = S[BH_ + r0 + 4];
                bLo[nf][0] = S[BL_ + r0];
                bLo[nf][1] = S[BL_ + r0 + 4];
            }
            #pragma unroll
            for (int mf = 0; mf < 2; mf++)
                #pragma unroll
                for (int nf = 0; nf < 4; nf++) {
                    mma_f16(acc[mf][nf], aHi[mf], bHi[nf]);
                    mma_f16(acc[mf][nf], aHi[mf], bLo[nf]);
                    mma_f16(acc[mf][nf], aLo[mf], bHi[nf]);
                }
        }
        // no trailing sync — next chunk writes the other buffer
    }
    __syncthreads();   // protect epilogue smem reuse

    // ---- epilogue: write H tile + fused BN partial sums (deterministic) ----
    #pragma unroll
    for (int mf = 0; mf < 2; mf++) {
        const int r = m0 + wm * 32 + mf * 16 + qr;
        #pragma unroll
        for (int nf = 0; nf < 4; nf++) {
            const int col = n0 + wn * 32 + nf * 8 + qc * 2;
            *(float2*)&H[(size_t)r * N_ + col] =
                make_float2(acc[mf][nf][0], acc[mf][nf][1]);
            *(float2*)&H[(size_t)(r + 8) * N_ + col] =
                make_float2(acc[mf][nf][2], acc[mf][nf][3]);
        }
    }

    float cs[4][2], cq[4][2];
    #pragma unroll
    for (int nf = 0; nf < 4; nf++)
        #pragma unroll
        for (int j = 0; j < 2; j++) {
            float s = 0.f, q = 0.f;
            #pragma unroll
            for (int mf = 0; mf < 2; mf++) {
                float v0 = acc[mf][nf][j], v1 = acc[mf][nf][j + 2];
                s += v0 + v1;
                q += v0 * v0 + v1 * v1;
            }
            #pragma unroll
            for (int off = 16; off >= 4; off >>= 1) {
                s += __shfl_down_sync(0xffffffffu, s, off);
                q += __shfl_down_sync(0xffffffffu, q, off);
            }
            cs[nf][j] = s; cq[nf][j] = q;
        }
    float* red = (float*)sm;
    if (qr == 0) {
        #pragma unroll
        for (int nf = 0; nf < 4; nf++)
            #pragma unroll
            for (int j = 0; j < 2; j++) {
                int o = (((wm * 4 + wn) * 4 + nf) * 4 + qc) * 2 + j;
                red[o] = cs[nf][j];
                red[512 + o] = cq[nf][j];
            }
    }
    __syncthreads();
    if (tid < 128) {
        const int col = tid;
        const int wn2 = col >> 5, rem = col & 31;
        const int nf2 = rem >> 3, r2 = rem & 7;
        const int qc2 = r2 >> 1, j2 = r2 & 1;
        float s = 0.f, q = 0.f;
        #pragma unroll
        for (int wm2 = 0; wm2 < 4; wm2++) {
            int o = (((wm2 * 4 + wn2) * 4 + nf2) * 4 + qc2) * 2 + j2;
            s += red[o];
            q += red[512 + o];
        }
        int chunk = blockIdx.z * 64 + blockIdx.y;
        d_psum[(size_t)chunk * N_ + n0 + col] = s;
        d_psq [(size_t)chunk * N_ + n0 + col] = q;
    }
}

// ================= BN finalize (+ zero spatial counters) ===============
__global__ __launch_bounds__(256) void bn_final_kernel(
    const float* __restrict__ g1, const float* __restrict__ b1,
    const float* __restrict__ g2, const float* __restrict__ b2)
{
    const int idx = blockIdx.x * 256 + threadIdx.x;   // mat*N_ + col
    const int mat = idx >> 10;
    const int col = idx & (N_ - 1);
    float s = 0.f, sq = 0.f;
    for (int c = 0; c < 64; c++) {
        s  += d_psum[(size_t)(mat * 64 + c) * N_ + col];
        sq += d_psq [(size_t)(mat * 64 + c) * N_ + col];
    }
    const float inv = 1.f / (float)TB;
    float mean = s * inv;
    float var = sq * inv - mean * mean;
    float gamma = mat ? g2[col] : g1[col];
    float beta  = mat ? b2[col] : b1[col];
    float scale = gamma * rsqrtf(var + EPS);
    d_scale[idx] = scale;
    d_bias[idx] = beta - mean * scale;
    #pragma unroll
    for (int j = 0; j < 4; j++) d_ssum_i[idx * 4 + j] = 0;
}

// ============ Merged LIF branches (spatial + temporal) =================
// blocks [0,512): branch1 (1 feat/thread, ballot counting).
// blocks [512,768): branch2, 2 elems/thread via float2.
__global__ __launch_bounds__(256) void branches_kernel()
{
    const int bx = blockIdx.x;
    const int tid = threadIdx.x;
    if (bx < 512) {
        __shared__ int ssum[T_];
        const int b = bx & 127;
        const int f = (bx >> 7) * 256 + tid;
        const int lane = tid & 31;
        if (tid < T_) ssum[tid] = 0;
        __syncthreads();
        const float sc = d_scale[f];
        const float bi = d_bias[f];
        float v = 0.f;
        for (int t = 0; t < T_; t++) {
            float h = fmaf(d_h1[(size_t)(t * B_ + b) * N_ + f], sc, bi);
            v = fmaf(v, 0.5f, h);
            bool s = (v >= VTH);
            if (s) v = 0.f;
            unsigned bal = __ballot_sync(0xffffffffu, s);
            if (lane == 0) atomicAdd(&ssum[t], __popc(bal));
        }
        __syncthreads();
        if (tid < T_) atomicAdd(&d_ssum_i[tid * B_ + b], ssum[tid]);
    } else {
        const int g = ((bx - 512) * 256 + tid) * 2;     // pair base
        const int m = g & (N_ - 1);
        const float2 sc = *(const float2*)&d_scale[N_ + m];
        const float2 bi = *(const float2*)&d_bias[N_ + m];
        float v0 = 0.f, v1 = 0.f;
        int c0 = 0, c1 = 0;
        #pragma unroll 4
        for (int t = 0; t < T_; t++) {
            float2 h2 = *(const float2*)&d_h2[(size_t)t * BN_ + g];
            float h0 = fmaf(h2.x, sc.x, bi.x);
            float h1 = fmaf(h2.y, sc.y, bi.y);
            v0 = fmaf(v0, 0.5f, h0);
            v1 = fmaf(v1, 0.5f, h1);
            if (v0 >= VTH) { c0++; v0 = 0.f; }
            if (v1 >= VTH) { c1++; v1 = 0.f; }
        }
        *(float2*)&d_tsum[g] = make_float2((float)c0, (float)c1);
    }
}

// ============ Final: gate LIFs + output (2 elems/thread) ===============
__global__ __launch_bounds__(256) void final_kernel(
    const float* __restrict__ X, float* __restrict__ out)
{
    const int g = (blockIdx.x * 256 + threadIdx.x) * 2;  // pair base (b*N_+n)
    const int b = g >> 10;
    __shared__ float ss[T_];
    if (threadIdx.x < T_) ss[threadIdx.x] = (float)d_ssum_i[threadIdx.x * B_ + b];
    __syncthreads();

    const float2 ts = *(const float2*)&d_tsum[g];
    float va0 = 0.f, vb0 = 0.f, va1 = 0.f, vb1 = 0.f;
    #pragma unroll 4
    for (int t = 0; t < T_; t++) {
        float2 xt = *(const float2*)&X[(size_t)t * BN_ + g];
        float st = ss[t];
        va0 = fmaf(va0, 0.5f, xt.x * st);
        va1 = fmaf(va1, 0.5f, xt.y * st);
        float a0 = 0.f, a1 = 0.f;
        if (va0 >= VTH) { a0 = 1.f; va0 = 0.f; }
        if (va1 >= VTH) { a1 = 1.f; va1 = 0.f; }
        vb0 = fmaf(vb0, 0.5f, xt.x * ts.x);
        vb1 = fmaf(vb1, 0.5f, xt.y * ts.y);
        float b0 = 0.f, b1 = 0.f;
        if (vb0 >= VTH) { b0 = 1.f; vb0 = 0.f; }
        if (vb1 >= VTH) { b1 = 1.f; vb1 = 0.f; }
        *(float2*)&out[(size_t)t * BN_ + g] =
            make_float2(xt.x + a0 * b0, xt.y + a1 * b1);
    }
}

// ======================================================================
extern "C" void kernel_launch(void* const* d_in, const int* in_sizes, int n_in,
                              void* d_out, int out_size)
{
    const float* x  = (const float*)d_in[0];
    const float* W1 = (const float*)d_in[1];
    const float* g1 = (const float*)d_in[2];
    const float* b1 = (const float*)d_in[3];
    const float* W2 = (const float*)d_in[4];
    const float* g2 = (const float*)d_in[5];
    const float* b2 = (const float*)d_in[6];
    float* out = (float*)d_out;

    cudaFuncSetAttribute(gemm_tc, cudaFuncAttributeMaxDynamicSharedMemorySize, SMEM_BYTES);

    // 1. Both GEMMs (mma.sync 3xFP16, single-sync pipeline, fused BN partials)
    dim3 ggrid(N_ / 128, TB / 128, 2);
    gemm_tc<<<ggrid, 512, SMEM_BYTES>>>(x, W1, W2);

    // 2. BN finalize (+ zero spike counters)
    bn_final_kernel<<<(2 * N_) / 256, 256>>>(g1, b1, g2, b2);

    // 3. Merged LIF branches (512 branch1 blocks + 256 branch2 blocks)
    branches_kernel<<<768, 256>>>();

    // 4. Fused gate LIFs + output
    final_kernel<<<BN_ / 512, 256>>>(x, out);
}